// round 13
// baseline (speedup 1.0000x reference)
#include <cuda_runtime.h>
#include <cuda_bf16.h>
#include <cstdint>

// PairwiseScore via warp-level bf16 mma.sync, bulk-copy pipelined.
// out[b,i,j] = (m_i + m_j + MLP3(g_i,g_j))/3,  B=2,N=256,E=512,H=150 (pad 160).
// One CTA per (b,i), 256 threads (8 warps), j-tiles of 128.
// B weight tiles stream via ONE cp.async.bulk (20KB) per chunk into a double
// buffer (2 mbarriers, parity (t>>1)&1). A1 double-buffered, filled one chunk
// ahead. Epilogue-1 runs at the END of chunk u==7 (no extra sync). GEMM2's
// third k-chunk is half-width; its A tile aliases the idle A1 buffer (jt-dep).

namespace {
constexpr int B_ = 2, N_ = 256, E_ = 512, H_ = 150;
constexpr int HS = 160;   // padded H
}

// ---- device scratch (no cudaMalloc allowed) ----
__device__ float g_HI[B_ * N_ * HS];
__device__ float g_HJ[B_ * N_ * HS];
// W1c^T bf16 pre-swizzled: 8 chunks x [160 n][64 k] (20480 B each)
__device__ __align__(16) unsigned char g_W1cT[8 * 20480];
// W2^T bf16 pre-swizzled: 3 chunks x [160 n][64 k]
__device__ __align__(16) unsigned char g_W2T[3 * 20480];
// g bf16 pre-swizzled A-tiles: 32 tiles [(b*2+jt)*8+u] x [128 r][8 seg'] x 16B
__device__ __align__(16) unsigned char g_sw[32 * 16384];

// swizzled byte offset inside a [rows][64] bf16 tile (128 B rows, 8x16B segs)
__device__ __forceinline__ int swz(int row, int k) {
    return row * 128 + (((k >> 3) ^ (row & 7)) * 16) + (k & 7) * 2;
}
__device__ __forceinline__ uint32_t smem_u32(const void* p) {
    uint32_t a;
    asm("{ .reg .u64 t; cvta.to.shared.u64 t, %1; cvt.u32.u64 %0, t; }" : "=r"(a) : "l"(p));
    return a;
}
#define CVT_BF2(res, lo, hi) asm("cvt.rn.bf16x2.f32 %0, %1, %2;" : "=r"(res) : "f"(hi), "f"(lo))
#define MULB2(res, a, b) asm("mul.bf16x2 %0, %1, %2;" : "=r"(res) : "r"(a), "r"(b))

#define MBAR_INIT(mb, c) \
    asm volatile("mbarrier.init.shared.b64 [%0], %1;" :: "r"(mb), "r"(c) : "memory")
#define MBAR_EXPECT_TX(mb, bytes) \
    asm volatile("mbarrier.arrive.expect_tx.shared.b64 _, [%0], %1;" :: "r"(mb), "r"(bytes) : "memory")
#define BULK_G2S(dst, src, bytes, mb) \
    asm volatile("cp.async.bulk.shared::cluster.global.mbarrier::complete_tx::bytes [%0], [%1], %2, [%3];" \
                 :: "r"(dst), "l"(src), "r"(bytes), "r"(mb) : "memory")

__device__ __forceinline__ void mbar_wait(uint32_t mb, uint32_t parity) {
    uint32_t done;
    asm volatile(
        "{\n\t.reg .pred p;\n\t"
        "mbarrier.try_wait.parity.acquire.cta.shared::cta.b64 p, [%1], %2;\n\t"
        "selp.b32 %0, 1, 0, p;\n\t}"
        : "=r"(done) : "r"(mb), "r"(parity) : "memory");
    if (!done) {
        asm volatile(
            "{\n\t.reg .pred P1;\n\t"
            "WL_%=:\n\t"
            "mbarrier.try_wait.parity.acquire.cta.shared::cta.b64 P1, [%0], %1, 0x989680;\n\t"
            "@P1 bra.uni WD_%=;\n\t"
            "bra.uni WL_%=;\n\t"
            "WD_%=:\n\t}"
            :: "r"(mb), "r"(parity) : "memory");
    }
}

__device__ __forceinline__ void mma16816(float* d, const uint32_t* a, const uint32_t* bf) {
    asm volatile("mma.sync.aligned.m16n8k16.row.col.f32.bf16.bf16.f32 "
                 "{%0,%1,%2,%3}, {%4,%5,%6,%7}, {%8,%9}, {%0,%1,%2,%3};"
                 : "+f"(d[0]), "+f"(d[1]), "+f"(d[2]), "+f"(d[3])
                 : "r"(a[0]), "r"(a[1]), "r"(a[2]), "r"(a[3]), "r"(bf[0]), "r"(bf[1]));
}

// B-fragment loads for one ks step: warp (ns) slice, 5 n-tiles.
__device__ __forceinline__ void load_b_frags(uint32_t bBase, int ns, int lane, int ks,
                                             uint32_t (*bfr)[2]) {
#pragma unroll
    for (int ntp = 0; ntp < 2; ntp++) {     // nt pairs (0,1),(2,3) via x4
        int grp = lane >> 3;
        int ntv = ntp * 2 + (grp >> 1);
        int seg = ks * 2 + (grp & 1);
        int nrow = ns * 40 + ntv * 8 + (lane & 7);
        uint32_t bd = bBase + nrow * 128 + ((seg ^ (nrow & 7)) * 16);
        asm volatile("ldmatrix.sync.aligned.m8n8.x4.shared.b16 {%0,%1,%2,%3}, [%4];"
                     : "=r"(bfr[ntp * 2][0]), "=r"(bfr[ntp * 2][1]),
                       "=r"(bfr[ntp * 2 + 1][0]), "=r"(bfr[ntp * 2 + 1][1])
                     : "r"(bd));
    }
    {                                        // nt = 4 via x2
        int nrow = ns * 40 + 32 + (lane & 7);
        int seg = ks * 2 + ((lane >> 3) & 1);
        uint32_t bd = bBase + nrow * 128 + ((seg ^ (nrow & 7)) * 16);
        asm volatile("ldmatrix.sync.aligned.m8n8.x2.shared.b16 {%0,%1}, [%2];"
                     : "=r"(bfr[4][0]), "=r"(bfr[4][1]) : "r"(bd));
    }
}

// One k-chunk (NKS ks-steps of 16). A tile [128][64] at aBase, B [160][64] at bBase.
// Warp (mh,ns): rows mh*64..+63, cols ns*40..+39 -> acc[4 mt][5 nt][4].
template <int NKS>
__device__ __forceinline__ void gemm_chunk(uint32_t aBase, uint32_t bBase,
                                           int mh, int ns, int lane, float (*acc)[5][4]) {
#pragma unroll
    for (int ks = 0; ks < NKS; ks++) {
        uint32_t a[4][4];
#pragma unroll
        for (int mt = 0; mt < 4; mt++) {
            int row = mh * 64 + mt * 16 + ((lane >> 3) & 1) * 8 + (lane & 7);
            int seg = ks * 2 + (lane >> 4);
            uint32_t ad = aBase + row * 128 + ((seg ^ (row & 7)) * 16);
            asm volatile("ldmatrix.sync.aligned.m8n8.x4.shared.b16 {%0,%1,%2,%3}, [%4];"
                         : "=r"(a[mt][0]), "=r"(a[mt][1]), "=r"(a[mt][2]), "=r"(a[mt][3])
                         : "r"(ad));
        }
        uint32_t bfr[5][2];
        load_b_frags(bBase, ns, lane, ks, bfr);
#pragma unroll
        for (int nt = 0; nt < 5; nt++)
#pragma unroll
            for (int mt = 0; mt < 4; mt++) mma16816(acc[mt][nt], a[mt], bfr[nt]);
    }
}

// smem byte map
constexpr int SM_HI  = 0;        // 160 f (640 B)
constexpr int SM_W3  = 640;      // 160 f
constexpr int SM_B2  = 1280;     // 160 f
constexpr int SM_GIB = 1920;     // 512 bf16 (1024 B)
constexpr int SM_RED = 2944;     // 128*4 f (2048 B)
constexpr int SM_MBAR = 4992;    // 2 mbarriers (16 B)
constexpr int SM_A1A = 5120;     // A1 buf 0 (16384); aliases A2 chunk 2 for jt=0
constexpr int SM_A1B = 21504;    // A1 buf 1 (16384); aliases A2 chunk 2 for jt=1
constexpr int SM_B0  = 37888;    // [160][64] bf16 swz (20480) x2 double buffer
constexpr int SM_A2  = 78848;    // A2 chunks 0,1 (2 x 16384)
constexpr int SMEM_BYTES = 111616;

// A-fill: A1 = bf16(g_j) * bf16(g_i) for chunk u of j-tile jt, into dstOff.
__device__ __forceinline__ void a_fill(char* smc, int dstOff, int b, int jt, int u, int tid) {
    const unsigned char* gsrc = g_sw + ((b * 2 + jt) * 8 + u) * 16384;
#pragma unroll
    for (int s4 = 0; s4 < 4; s4++) {
        int slot = s4 * 256 + tid;           // 0..1023
        uint4 gv = *(const uint4*)(gsrc + slot * 16);
        int r = slot >> 3, sp = slot & 7;
        uint4 iv = *(const uint4*)(smc + SM_GIB + u * 128 + ((sp ^ (r & 7)) * 16));
        uint4 o;
        MULB2(o.x, gv.x, iv.x);
        MULB2(o.y, gv.y, iv.y);
        MULB2(o.z, gv.z, iv.z);
        MULB2(o.w, gv.w, iv.w);
        *(uint4*)(smc + dstOff + slot * 16) = o;
    }
}

// ---------------------------------------------------------------------------
// Merged prep kernel (vectorized W stores).
// bb 0..63    : HI/HJ (8 rows each)
// bb 64..103  : W1cT  (10240 threads, 1 uint4 store each)
// bb 104..118 : W2T   (3840 threads)
// bb 119..246 : g -> g_sw bf16 pre-swizzled A tiles
// ---------------------------------------------------------------------------
__global__ void __launch_bounds__(256) k_prep(
    const float* __restrict__ g, const float* __restrict__ W1,
    const float* __restrict__ b1, const float* __restrict__ W2)
{
    const int bb = blockIdx.x;
    const int tid = threadIdx.x;
    if (bb >= 64) {
        if (bb < 104) {           // W1cT: pack 8 bf16 = one 16B swizzle seg
            int idx = (bb - 64) * 256 + tid;            // 0..10239
            int c = idx / 1280, r = idx % 1280;
            int s = r / 160, n = r % 160;
            const float* src = W1 + (2 * E_ + c * 64 + s * 8) * H_ + n;
            uint4 o;
            uint32_t* op = (uint32_t*)&o;
            bool v = (n < H_);
#pragma unroll
            for (int d = 0; d < 4; d++) {
                float lo = v ? src[(2 * d) * H_] : 0.f;
                float hi = v ? src[(2 * d + 1) * H_] : 0.f;
                CVT_BF2(op[d], lo, hi);
            }
            *(uint4*)(g_W1cT + c * 20480 + n * 128 + ((s ^ (n & 7)) * 16)) = o;
        } else if (bb < 119) {    // W2T
            int idx = (bb - 104) * 256 + tid;           // 0..3839
            int c = idx / 1280, r = idx % 1280;
            int s = r / 160, n = r % 160;
            int k0 = c * 64 + s * 8;
            const float* src = W2 + k0 * H_ + n;
            uint4 o;
            uint32_t* op = (uint32_t*)&o;
            bool v = (n < H_);
#pragma unroll
            for (int d = 0; d < 4; d++) {
                float lo = (v && k0 + 2 * d < H_) ? src[(2 * d) * H_] : 0.f;
                float hi = (v && k0 + 2 * d + 1 < H_) ? src[(2 * d + 1) * H_] : 0.f;
                CVT_BF2(op[d], lo, hi);
            }
            *(uint4*)(g_W2T + c * 20480 + n * 128 + ((s ^ (n & 7)) * 16)) = o;
        } else {                  // g_sw
            int slot = (bb - 119) * 256 + tid;          // 32768 16B slots
            int tile = slot >> 10, q = slot & 1023;
            int r = q >> 3, sp = q & 7;
            int b = tile >> 4, jt = (tile >> 3) & 1, u = tile & 7;
            int grow = b * 256 + jt * 128 + r;
            int e0 = u * 64 + ((sp ^ (r & 7)) * 8);
            const float4* src = (const float4*)(g + grow * E_ + e0);
            float4 v0 = src[0], v1 = src[1];
            uint4 o;
            CVT_BF2(o.x, v0.x, v0.y);
            CVT_BF2(o.y, v0.z, v0.w);
            CVT_BF2(o.z, v1.x, v1.y);
            CVT_BF2(o.w, v1.z, v1.w);
            *(uint4*)(g_sw + slot * 16) = o;
        }
        return;
    }
    // HI/HJ: 8 rows per block, tx = h lane (5 h each, stride 32), ty = row
    __shared__ float sm[8 * 33 + 2 * 32 * 152 + 64];
    float* gs = sm;
    float* wa = sm + 8 * 33;
    float* wb = wa + 32 * 152;
    const int tx = tid & 31, ty = tid >> 5;
    const int r0 = bb * 8;
    float acca[5] = {0, 0, 0, 0, 0}, accb[5] = {0, 0, 0, 0, 0};
    for (int ec = 0; ec < E_; ec += 32) {
        __syncthreads();
        { int jj = tid >> 5, ee = tid & 31; gs[jj * 33 + ee] = g[(r0 + jj) * E_ + ec + ee]; }
        for (int q = tid; q < 32 * H_; q += 256) {
            int r = q / H_, c = q % H_;
            wa[r * 152 + c] = W1[(ec + r) * H_ + c];
            wb[r * 152 + c] = W1[(E_ + ec + r) * H_ + c];
        }
        __syncthreads();
#pragma unroll 8
        for (int e = 0; e < 32; e++) {
            float a = gs[ty * 33 + e];
#pragma unroll
            for (int k = 0; k < 5; k++) {
                acca[k] += a * wa[e * 152 + tx + 32 * k];
                accb[k] += a * wb[e * 152 + tx + 32 * k];
            }
        }
    }
    const int row = r0 + ty;
#pragma unroll
    for (int k = 0; k < 5; k++) {
        int h = tx + 32 * k;     // 0..159
        bool v = (h < H_);
        g_HI[row * HS + h] = v ? (acca[k] + b1[h]) : 0.f;
        g_HJ[row * HS + h] = v ? accb[k] : 0.f;
    }
}

// ---------------------------------------------------------------------------
// Main kernel: one CTA per (b,i), 256 threads (8 warps), 2 CTAs/SM.
// ---------------------------------------------------------------------------
__global__ void __launch_bounds__(256, 2) k_main(
    const float* __restrict__ g, const float* __restrict__ ment,
    const float* __restrict__ b2, const float* __restrict__ W3,
    const float* __restrict__ b3, float* __restrict__ out)
{
    extern __shared__ char smc[];
    float* smf = (float*)smc;
    const uint32_t sb = smem_u32(smc);
    const int tid = threadIdx.x, w = tid >> 5, lane = tid & 31;
    const int mh = w & 1, ns = w >> 1;
    const int b = blockIdx.x >> 8;
    const int rowi = blockIdx.x;

    if (tid == 0) {
        MBAR_INIT(sb + SM_MBAR, 1);
        MBAR_INIT(sb + SM_MBAR + 8, 1);
    }
    __syncthreads();          // mbarrier init visible
    if (tid == 0) {           // B(0): W1c chunk 0 -> buffer 0, one bulk copy
        MBAR_EXPECT_TX(sb + SM_MBAR, 20480u);
        BULK_G2S(sb + SM_B0, (const char*)g_W1cT, 20480u, sb + SM_MBAR);
    }

    {   // gi -> bf16 in smem
        float2 v = *(const float2*)(g + rowi * E_ + tid * 2);
        uint32_t pk;
        CVT_BF2(pk, v.x, v.y);
        *(uint32_t*)(smc + SM_GIB + tid * 4) = pk;
    }
    for (int q = tid; q < HS; q += 256) {
        smf[SM_HI / 4 + q] = g_HI[rowi * HS + q];   // already zero-padded
        smf[SM_W3 / 4 + q] = (q < H_) ? W3[q] : 0.f;
        smf[SM_B2 / 4 + q] = (q < H_) ? b2[q] : 0.f;
    }
    __syncthreads();                 // gi visible to a_fill
    a_fill(smc, SM_A1A, b, 0, 0, tid);   // prologue: fill chunk 0 into A1[0]

    const float mi = ment[rowi];
    const float b3v = b3[0];
    float acc[4][5][4];   // shared between GEMM1 and GEMM2 (reset at u==0 / epi-1)

    for (int t = 0; t < 22; t++) {
        const int u = (t >= 11) ? t - 11 : t;        // chunk id in j-tile stream
        const int jt = (t >= 11) ? 1 : 0;
        const int jb = jt * 128;
        // A2 chunk-2 alias: the A1 buffer idle during this j-tile's GEMM2 span
        const int a2c2 = jt ? SM_A1B : SM_A1A;

        __syncthreads();   // gemm(t-1)+epi(t-1) done everywhere; fill(t)/A2 visible

        // issue single bulk copy for B(t+1) into alternate buffer + A-prefetch
        if (t + 1 < 22) {
            const int t2 = t + 1;
            const int u2 = (t2 >= 11) ? t2 - 11 : t2;
            if (tid == 0) {
                const char* src = (u2 < 8) ? (const char*)g_W1cT + u2 * 20480
                                           : (const char*)g_W2T + (u2 - 8) * 20480;
                uint32_t mb2 = sb + SM_MBAR + (uint32_t)(t2 & 1) * 8;
                MBAR_EXPECT_TX(mb2, 20480u);
                BULK_G2S(sb + SM_B0 + ((t2 & 1) ? 20480u : 0u), src, 20480u, mb2);
            }
            if (u2 < 8)
                a_fill(smc, (t2 & 1) ? SM_A1B : SM_A1A, b, (t2 >= 11) ? 1 : 0, u2, tid);
        }

        if (u == 0) {
#pragma unroll
            for (int mt = 0; mt < 4; mt++)
#pragma unroll
                for (int nt = 0; nt < 5; nt++)
#pragma unroll
                    for (int q = 0; q < 4; q++) acc[mt][nt][q] = 0.f;
        }

        // wait for B(t) bulk copy (parity: load number (t>>1) on this mbar)
        mbar_wait(sb + SM_MBAR + (uint32_t)(t & 1) * 8, (uint32_t)((t >> 1) & 1));

        uint32_t curB = sb + SM_B0 + ((t & 1) ? 20480u : 0u);
        if (u < 8) {
            gemm_chunk<4>(sb + ((t & 1) ? SM_A1B : SM_A1A), curB, mh, ns, lane, acc);
        } else if (u == 8) {
            gemm_chunk<4>(sb + SM_A2, curB, mh, ns, lane, acc);
        } else if (u == 9) {
            gemm_chunk<4>(sb + SM_A2 + 16384, curB, mh, ns, lane, acc);
        } else {
            gemm_chunk<2>(sb + (uint32_t)a2c2, curB, mh, ns, lane, acc);  // k 128..159
        }

        if (u == 7) {
            // epilogue 1 (acc is per-warp complete): A2 = bf16(relu(acc+HI+HJ)),
            // then reset acc. Next loop-top sync publishes A2 before gemm(8).
            const float* hjb = g_HJ + (b * N_ + jb) * HS;
#pragma unroll
            for (int mt = 0; mt < 4; mt++) {
                int r0 = mh * 64 + mt * 16 + (lane >> 2);
#pragma unroll
                for (int nt = 0; nt < 5; nt++) {
                    int h = ns * 40 + nt * 8 + (lane & 3) * 2;
                    float2 hi2 = *(const float2*)(smf + SM_HI / 4 + h);
                    float2 hj0 = *(const float2*)(hjb + r0 * HS + h);
                    float2 hj8 = *(const float2*)(hjb + (r0 + 8) * HS + h);
                    float v0 = fmaxf(acc[mt][nt][0] + hi2.x + hj0.x, 0.f);
                    float v1 = fmaxf(acc[mt][nt][1] + hi2.y + hj0.y, 0.f);
                    float v2 = fmaxf(acc[mt][nt][2] + hi2.x + hj8.x, 0.f);
                    float v3 = fmaxf(acc[mt][nt][3] + hi2.y + hj8.y, 0.f);
                    int base = (h < 64) ? SM_A2 : (h < 128) ? (SM_A2 + 16384) : a2c2;
                    int kk = h & 63;
                    uint32_t pk;
                    CVT_BF2(pk, v0, v1);
                    *(uint32_t*)(smc + base + swz(r0, kk)) = pk;
                    CVT_BF2(pk, v2, v3);
                    *(uint32_t*)(smc + base + swz(r0 + 8, kk)) = pk;
                    acc[mt][nt][0] = acc[mt][nt][1] = acc[mt][nt][2] = acc[mt][nt][3] = 0.f;
                }
            }
        } else if (u == 10) {
            // epilogue 2: relu(acc + b2) . w3, cross-warp reduce, write out
            float rs0[4], rs8[4];
#pragma unroll
            for (int mt = 0; mt < 4; mt++) {
                float s0 = 0.f, s8 = 0.f;
#pragma unroll
                for (int nt = 0; nt < 5; nt++) {
                    int h = ns * 40 + nt * 8 + (lane & 3) * 2;
                    float w30 = smf[SM_W3 / 4 + h], w31 = smf[SM_W3 / 4 + h + 1];
                    float bb0 = smf[SM_B2 / 4 + h], bb1 = smf[SM_B2 / 4 + h + 1];
                    s0 += fmaxf(acc[mt][nt][0] + bb0, 0.f) * w30
                        + fmaxf(acc[mt][nt][1] + bb1, 0.f) * w31;
                    s8 += fmaxf(acc[mt][nt][2] + bb0, 0.f) * w30
                        + fmaxf(acc[mt][nt][3] + bb1, 0.f) * w31;
                }
                s0 += __shfl_xor_sync(0xffffffffu, s0, 1);
                s0 += __shfl_xor_sync(0xffffffffu, s0, 2);
                s8 += __shfl_xor_sync(0xffffffffu, s8, 1);
                s8 += __shfl_xor_sync(0xffffffffu, s8, 2);
                rs0[mt] = s0; rs8[mt] = s8;
            }
            if ((lane & 3) == 0) {
                int rr = lane >> 2;
#pragma unroll
                for (int mt = 0; mt < 4; mt++) {
                    smf[SM_RED / 4 + (mh * 64 + mt * 16 + rr) * 4 + ns] = rs0[mt];
                    smf[SM_RED / 4 + (mh * 64 + mt * 16 + 8 + rr) * 4 + ns] = rs8[mt];
                }
            }
            __syncthreads();
            if (tid < 128) {
                float s = smf[SM_RED / 4 + tid * 4 + 0] + smf[SM_RED / 4 + tid * 4 + 1]
                        + smf[SM_RED / 4 + tid * 4 + 2] + smf[SM_RED / 4 + tid * 4 + 3];
                int j = jb + tid;
                out[rowi * N_ + j] = (mi + ment[b * N_ + j] + s + b3v) * (1.0f / 3.0f);
            }
        }
    }
}

// ---------------------------------------------------------------------------
extern "C" void kernel_launch(void* const* d_in, const int* in_sizes, int n_in,
                              void* d_out, int out_size)
{
    const float* g  = (const float*)d_in[0];
    const float* m  = (const float*)d_in[1];
    const float* W1 = (const float*)d_in[2];
    const float* b1 = (const float*)d_in[3];
    const float* W2 = (const float*)d_in[4];
    const float* b2 = (const float*)d_in[5];
    const float* W3 = (const float*)d_in[6];
    const float* b3 = (const float*)d_in[7];
    float* out = (float*)d_out;

    (void)cudaFuncSetAttribute(k_main,
                               cudaFuncAttributeMaxDynamicSharedMemorySize, SMEM_BYTES);

    k_prep<<<247, 256>>>(g, W1, b1, W2);
    k_main<<<B_ * N_, 256, SMEM_BYTES>>>(g, m, b2, W3, b3, out);
}

// round 14
// speedup vs baseline: 1.4233x; 1.4233x over previous
#include <cuda_runtime.h>
#include <cuda_bf16.h>
#include <cstdint>

// PairwiseScore via warp-level bf16 mma.sync, bulk-copy pipelined.
// out[b,i,j] = (m_i + m_j + MLP3(g_i,g_j))/3,  B=2,N=256,E=512,H=150 (pad 160).
// One CTA per (b,i), 256 threads (8 warps), j-tiles of 128.
// B weight tiles stream via ONE cp.async.bulk (20KB) per chunk into a double
// buffer (2 mbarriers, parity (t>>1)&1). A1 double-buffered, filled one chunk
// ahead. Epilogue-1 runs at the END of chunk u==7. GEMM2's third k-chunk is
// half-width; its A tile aliases the idle A1 buffer (jt-dep).
// HI/HJ precompute is E-split 4-way across blocks with atomicAdd combine
// (g_HI/g_HJ zeroed by k_zero each launch).

namespace {
constexpr int B_ = 2, N_ = 256, E_ = 512, H_ = 150;
constexpr int HS = 160;   // padded H
}

// ---- device scratch (no cudaMalloc allowed) ----
__device__ float g_HI[B_ * N_ * HS];
__device__ float g_HJ[B_ * N_ * HS];
// W1c^T bf16 pre-swizzled: 8 chunks x [160 n][64 k] (20480 B each)
__device__ __align__(16) unsigned char g_W1cT[8 * 20480];
// W2^T bf16 pre-swizzled: 3 chunks x [160 n][64 k]
__device__ __align__(16) unsigned char g_W2T[3 * 20480];
// g bf16 pre-swizzled A-tiles: 32 tiles [(b*2+jt)*8+u] x [128 r][8 seg'] x 16B
__device__ __align__(16) unsigned char g_sw[32 * 16384];

// swizzled byte offset inside a [rows][64] bf16 tile (128 B rows, 8x16B segs)
__device__ __forceinline__ int swz(int row, int k) {
    return row * 128 + (((k >> 3) ^ (row & 7)) * 16) + (k & 7) * 2;
}
__device__ __forceinline__ uint32_t smem_u32(const void* p) {
    uint32_t a;
    asm("{ .reg .u64 t; cvta.to.shared.u64 t, %1; cvt.u32.u64 %0, t; }" : "=r"(a) : "l"(p));
    return a;
}
#define CVT_BF2(res, lo, hi) asm("cvt.rn.bf16x2.f32 %0, %1, %2;" : "=r"(res) : "f"(hi), "f"(lo))
#define MULB2(res, a, b) asm("mul.bf16x2 %0, %1, %2;" : "=r"(res) : "r"(a), "r"(b))

#define MBAR_INIT(mb, c) \
    asm volatile("mbarrier.init.shared.b64 [%0], %1;" :: "r"(mb), "r"(c) : "memory")
#define MBAR_EXPECT_TX(mb, bytes) \
    asm volatile("mbarrier.arrive.expect_tx.shared.b64 _, [%0], %1;" :: "r"(mb), "r"(bytes) : "memory")
#define BULK_G2S(dst, src, bytes, mb) \
    asm volatile("cp.async.bulk.shared::cluster.global.mbarrier::complete_tx::bytes [%0], [%1], %2, [%3];" \
                 :: "r"(dst), "l"(src), "r"(bytes), "r"(mb) : "memory")

__device__ __forceinline__ void mbar_wait(uint32_t mb, uint32_t parity) {
    uint32_t done;
    asm volatile(
        "{\n\t.reg .pred p;\n\t"
        "mbarrier.try_wait.parity.acquire.cta.shared::cta.b64 p, [%1], %2;\n\t"
        "selp.b32 %0, 1, 0, p;\n\t}"
        : "=r"(done) : "r"(mb), "r"(parity) : "memory");
    if (!done) {
        asm volatile(
            "{\n\t.reg .pred P1;\n\t"
            "WL_%=:\n\t"
            "mbarrier.try_wait.parity.acquire.cta.shared::cta.b64 P1, [%0], %1, 0x989680;\n\t"
            "@P1 bra.uni WD_%=;\n\t"
            "bra.uni WL_%=;\n\t"
            "WD_%=:\n\t}"
            :: "r"(mb), "r"(parity) : "memory");
    }
}

__device__ __forceinline__ void mma16816(float* d, const uint32_t* a, const uint32_t* bf) {
    asm volatile("mma.sync.aligned.m16n8k16.row.col.f32.bf16.bf16.f32 "
                 "{%0,%1,%2,%3}, {%4,%5,%6,%7}, {%8,%9}, {%0,%1,%2,%3};"
                 : "+f"(d[0]), "+f"(d[1]), "+f"(d[2]), "+f"(d[3])
                 : "r"(a[0]), "r"(a[1]), "r"(a[2]), "r"(a[3]), "r"(bf[0]), "r"(bf[1]));
}

// B-fragment loads for one ks step: warp (ns) slice, 5 n-tiles.
__device__ __forceinline__ void load_b_frags(uint32_t bBase, int ns, int lane, int ks,
                                             uint32_t (*bfr)[2]) {
#pragma unroll
    for (int ntp = 0; ntp < 2; ntp++) {     // nt pairs (0,1),(2,3) via x4
        int grp = lane >> 3;
        int ntv = ntp * 2 + (grp >> 1);
        int seg = ks * 2 + (grp & 1);
        int nrow = ns * 40 + ntv * 8 + (lane & 7);
        uint32_t bd = bBase + nrow * 128 + ((seg ^ (nrow & 7)) * 16);
        asm volatile("ldmatrix.sync.aligned.m8n8.x4.shared.b16 {%0,%1,%2,%3}, [%4];"
                     : "=r"(bfr[ntp * 2][0]), "=r"(bfr[ntp * 2][1]),
                       "=r"(bfr[ntp * 2 + 1][0]), "=r"(bfr[ntp * 2 + 1][1])
                     : "r"(bd));
    }
    {                                        // nt = 4 via x2
        int nrow = ns * 40 + 32 + (lane & 7);
        int seg = ks * 2 + ((lane >> 3) & 1);
        uint32_t bd = bBase + nrow * 128 + ((seg ^ (nrow & 7)) * 16);
        asm volatile("ldmatrix.sync.aligned.m8n8.x2.shared.b16 {%0,%1}, [%2];"
                     : "=r"(bfr[4][0]), "=r"(bfr[4][1]) : "r"(bd));
    }
}

// One k-chunk (NKS ks-steps of 16). A tile [128][64] at aBase, B [160][64] at bBase.
// Warp (mh,ns): rows mh*64..+63, cols ns*40..+39 -> acc[4 mt][5 nt][4].
template <int NKS>
__device__ __forceinline__ void gemm_chunk(uint32_t aBase, uint32_t bBase,
                                           int mh, int ns, int lane, float (*acc)[5][4]) {
#pragma unroll
    for (int ks = 0; ks < NKS; ks++) {
        uint32_t a[4][4];
#pragma unroll
        for (int mt = 0; mt < 4; mt++) {
            int row = mh * 64 + mt * 16 + ((lane >> 3) & 1) * 8 + (lane & 7);
            int seg = ks * 2 + (lane >> 4);
            uint32_t ad = aBase + row * 128 + ((seg ^ (row & 7)) * 16);
            asm volatile("ldmatrix.sync.aligned.m8n8.x4.shared.b16 {%0,%1,%2,%3}, [%4];"
                         : "=r"(a[mt][0]), "=r"(a[mt][1]), "=r"(a[mt][2]), "=r"(a[mt][3])
                         : "r"(ad));
        }
        uint32_t bfr[5][2];
        load_b_frags(bBase, ns, lane, ks, bfr);
#pragma unroll
        for (int nt = 0; nt < 5; nt++)
#pragma unroll
            for (int mt = 0; mt < 4; mt++) mma16816(acc[mt][nt], a[mt], bfr[nt]);
    }
}

// smem byte map
constexpr int SM_HI  = 0;        // 160 f (640 B)
constexpr int SM_W3  = 640;      // 160 f
constexpr int SM_B2  = 1280;     // 160 f
constexpr int SM_GIB = 1920;     // 512 bf16 (1024 B)
constexpr int SM_RED = 2944;     // 128*4 f (2048 B)
constexpr int SM_MBAR = 4992;    // 2 mbarriers (16 B)
constexpr int SM_A1A = 5120;     // A1 buf 0 (16384); aliases A2 chunk 2 for jt=0
constexpr int SM_A1B = 21504;    // A1 buf 1 (16384); aliases A2 chunk 2 for jt=1
constexpr int SM_B0  = 37888;    // [160][64] bf16 swz (20480) x2 double buffer
constexpr int SM_A2  = 78848;    // A2 chunks 0,1 (2 x 16384)
constexpr int SMEM_BYTES = 111616;

// A-fill: A1 = bf16(g_j) * bf16(g_i) for chunk u of j-tile jt, into dstOff.
__device__ __forceinline__ void a_fill(char* smc, int dstOff, int b, int jt, int u, int tid) {
    const unsigned char* gsrc = g_sw + ((b * 2 + jt) * 8 + u) * 16384;
#pragma unroll
    for (int s4 = 0; s4 < 4; s4++) {
        int slot = s4 * 256 + tid;           // 0..1023
        uint4 gv = *(const uint4*)(gsrc + slot * 16);
        int r = slot >> 3, sp = slot & 7;
        uint4 iv = *(const uint4*)(smc + SM_GIB + u * 128 + ((sp ^ (r & 7)) * 16));
        uint4 o;
        MULB2(o.x, gv.x, iv.x);
        MULB2(o.y, gv.y, iv.y);
        MULB2(o.z, gv.z, iv.z);
        MULB2(o.w, gv.w, iv.w);
        *(uint4*)(smc + dstOff + slot * 16) = o;
    }
}

// ---------------------------------------------------------------------------
// k_zero: re-zero g_HI/g_HJ every launch (graph replays; atomics accumulate).
// ---------------------------------------------------------------------------
__global__ void __launch_bounds__(256) k_zero() {
    int i = blockIdx.x * 256 + threadIdx.x;
    if (i < B_ * N_ * HS) {
        g_HI[i] = 0.f;
        g_HJ[i] = 0.f;
    }
}

// ---------------------------------------------------------------------------
// Merged prep kernel.
// bb 0..511   : HI/HJ, E-split: gb=bb>>2 (4 rows), ec4=bb&3 (128-wide E chunk);
//               partials combined via atomicAdd (b1 added by ec4==0 only).
// bb 512..551 : W1cT (vectorized uint4 stores)
// bb 552..566 : W2T
// bb 567..694 : g -> g_sw bf16 pre-swizzled A tiles
// ---------------------------------------------------------------------------
__global__ void __launch_bounds__(256) k_prep(
    const float* __restrict__ g, const float* __restrict__ W1,
    const float* __restrict__ b1, const float* __restrict__ W2)
{
    const int bb = blockIdx.x;
    const int tid = threadIdx.x;
    if (bb >= 512) {
        if (bb < 552) {           // W1cT: pack 8 bf16 = one 16B swizzle seg
            int idx = (bb - 512) * 256 + tid;           // 0..10239
            int c = idx / 1280, r = idx % 1280;
            int s = r / 160, n = r % 160;
            const float* src = W1 + (2 * E_ + c * 64 + s * 8) * H_ + n;
            uint4 o;
            uint32_t* op = (uint32_t*)&o;
            bool v = (n < H_);
#pragma unroll
            for (int d = 0; d < 4; d++) {
                float lo = v ? src[(2 * d) * H_] : 0.f;
                float hi = v ? src[(2 * d + 1) * H_] : 0.f;
                CVT_BF2(op[d], lo, hi);
            }
            *(uint4*)(g_W1cT + c * 20480 + n * 128 + ((s ^ (n & 7)) * 16)) = o;
        } else if (bb < 567) {    // W2T
            int idx = (bb - 552) * 256 + tid;           // 0..3839
            int c = idx / 1280, r = idx % 1280;
            int s = r / 160, n = r % 160;
            int k0 = c * 64 + s * 8;
            const float* src = W2 + k0 * H_ + n;
            uint4 o;
            uint32_t* op = (uint32_t*)&o;
            bool v = (n < H_);
#pragma unroll
            for (int d = 0; d < 4; d++) {
                float lo = (v && k0 + 2 * d < H_) ? src[(2 * d) * H_] : 0.f;
                float hi = (v && k0 + 2 * d + 1 < H_) ? src[(2 * d + 1) * H_] : 0.f;
                CVT_BF2(op[d], lo, hi);
            }
            *(uint4*)(g_W2T + c * 20480 + n * 128 + ((s ^ (n & 7)) * 16)) = o;
        } else {                  // g_sw
            int slot = (bb - 567) * 256 + tid;          // 32768 16B slots
            int tile = slot >> 10, q = slot & 1023;
            int r = q >> 3, sp = q & 7;
            int b = tile >> 4, jt = (tile >> 3) & 1, u = tile & 7;
            int grow = b * 256 + jt * 128 + r;
            int e0 = u * 64 + ((sp ^ (r & 7)) * 8);
            const float4* src = (const float4*)(g + grow * E_ + e0);
            float4 v0 = src[0], v1 = src[1];
            uint4 o;
            CVT_BF2(o.x, v0.x, v0.y);
            CVT_BF2(o.y, v0.z, v0.w);
            CVT_BF2(o.z, v1.x, v1.y);
            CVT_BF2(o.w, v1.z, v1.w);
            *(uint4*)(g_sw + slot * 16) = o;
        }
        return;
    }
    // HI/HJ partial: 4 rows, E window [ec4*128, ec4*128+128)
    __shared__ float sm[4 * 33 + 2 * 32 * 152 + 32];
    float* gs = sm;
    float* wa = sm + 4 * 33;
    float* wb = wa + 32 * 152;
    const int tx = tid & 63, ty = tid >> 6;
    const int gb = bb >> 2, ec4 = bb & 3;
    const int r0 = gb * 4;
    const int e_base = ec4 * 128;
    const bool v2 = (tx < 22);    // h = tx+128 < 150
    float aA[3] = {0, 0, 0}, aB[3] = {0, 0, 0};
    for (int ec = e_base; ec < e_base + 128; ec += 32) {
        __syncthreads();
        if (tid < 128) {
            int jj = tid >> 5, ee = tid & 31;
            gs[jj * 33 + ee] = g[(r0 + jj) * E_ + ec + ee];
        }
        for (int q = tid; q < 32 * H_; q += 256) {
            int r = q / H_, c = q % H_;
            wa[r * 152 + c] = W1[(ec + r) * H_ + c];
            wb[r * 152 + c] = W1[(E_ + ec + r) * H_ + c];
        }
        __syncthreads();
#pragma unroll 8
        for (int e = 0; e < 32; e++) {
            float a = gs[ty * 33 + e];
            aA[0] += a * wa[e * 152 + tx];
            aA[1] += a * wa[e * 152 + tx + 64];
            if (v2) aA[2] += a * wa[e * 152 + tx + 128];
            aB[0] += a * wb[e * 152 + tx];
            aB[1] += a * wb[e * 152 + tx + 64];
            if (v2) aB[2] += a * wb[e * 152 + tx + 128];
        }
    }
    const int row = r0 + ty;
    const float bb0 = (ec4 == 0) ? b1[tx] : 0.f;
    const float bb1 = (ec4 == 0) ? b1[tx + 64] : 0.f;
    atomicAdd(&g_HI[row * HS + tx], aA[0] + bb0);
    atomicAdd(&g_HJ[row * HS + tx], aB[0]);
    atomicAdd(&g_HI[row * HS + tx + 64], aA[1] + bb1);
    atomicAdd(&g_HJ[row * HS + tx + 64], aB[1]);
    if (v2) {
        int h2 = tx + 128;
        const float bb2 = (ec4 == 0) ? b1[h2] : 0.f;
        atomicAdd(&g_HI[row * HS + h2], aA[2] + bb2);
        atomicAdd(&g_HJ[row * HS + h2], aB[2]);
    }
}

// ---------------------------------------------------------------------------
// Main kernel: one CTA per (b,i), 256 threads (8 warps), 2 CTAs/SM.
// (unchanged from R13)
// ---------------------------------------------------------------------------
__global__ void __launch_bounds__(256, 2) k_main(
    const float* __restrict__ g, const float* __restrict__ ment,
    const float* __restrict__ b2, const float* __restrict__ W3,
    const float* __restrict__ b3, float* __restrict__ out)
{
    extern __shared__ char smc[];
    float* smf = (float*)smc;
    const uint32_t sb = smem_u32(smc);
    const int tid = threadIdx.x, w = tid >> 5, lane = tid & 31;
    const int mh = w & 1, ns = w >> 1;
    const int b = blockIdx.x >> 8;
    const int rowi = blockIdx.x;

    if (tid == 0) {
        MBAR_INIT(sb + SM_MBAR, 1);
        MBAR_INIT(sb + SM_MBAR + 8, 1);
    }
    __syncthreads();          // mbarrier init visible
    if (tid == 0) {           // B(0): W1c chunk 0 -> buffer 0, one bulk copy
        MBAR_EXPECT_TX(sb + SM_MBAR, 20480u);
        BULK_G2S(sb + SM_B0, (const char*)g_W1cT, 20480u, sb + SM_MBAR);
    }

    {   // gi -> bf16 in smem
        float2 v = *(const float2*)(g + rowi * E_ + tid * 2);
        uint32_t pk;
        CVT_BF2(pk, v.x, v.y);
        *(uint32_t*)(smc + SM_GIB + tid * 4) = pk;
    }
    for (int q = tid; q < HS; q += 256) {
        smf[SM_HI / 4 + q] = g_HI[rowi * HS + q];   // already zero-padded
        smf[SM_W3 / 4 + q] = (q < H_) ? W3[q] : 0.f;
        smf[SM_B2 / 4 + q] = (q < H_) ? b2[q] : 0.f;
    }
    __syncthreads();                 // gi visible to a_fill
    a_fill(smc, SM_A1A, b, 0, 0, tid);   // prologue: fill chunk 0 into A1[0]

    const float mi = ment[rowi];
    const float b3v = b3[0];
    float acc[4][5][4];   // shared between GEMM1 and GEMM2 (reset at u==0 / epi-1)

    for (int t = 0; t < 22; t++) {
        const int u = (t >= 11) ? t - 11 : t;        // chunk id in j-tile stream
        const int jt = (t >= 11) ? 1 : 0;
        const int jb = jt * 128;
        // A2 chunk-2 alias: the A1 buffer idle during this j-tile's GEMM2 span
        const int a2c2 = jt ? SM_A1B : SM_A1A;

        __syncthreads();   // gemm(t-1)+epi(t-1) done everywhere; fill(t)/A2 visible

        // issue single bulk copy for B(t+1) into alternate buffer + A-prefetch
        if (t + 1 < 22) {
            const int t2 = t + 1;
            const int u2 = (t2 >= 11) ? t2 - 11 : t2;
            if (tid == 0) {
                const char* src = (u2 < 8) ? (const char*)g_W1cT + u2 * 20480
                                           : (const char*)g_W2T + (u2 - 8) * 20480;
                uint32_t mb2 = sb + SM_MBAR + (uint32_t)(t2 & 1) * 8;
                MBAR_EXPECT_TX(mb2, 20480u);
                BULK_G2S(sb + SM_B0 + ((t2 & 1) ? 20480u : 0u), src, 20480u, mb2);
            }
            if (u2 < 8)
                a_fill(smc, (t2 & 1) ? SM_A1B : SM_A1A, b, (t2 >= 11) ? 1 : 0, u2, tid);
        }

        if (u == 0) {
#pragma unroll
            for (int mt = 0; mt < 4; mt++)
#pragma unroll
                for (int nt = 0; nt < 5; nt++)
#pragma unroll
                    for (int q = 0; q < 4; q++) acc[mt][nt][q] = 0.f;
        }

        // wait for B(t) bulk copy (parity: load number (t>>1) on this mbar)
        mbar_wait(sb + SM_MBAR + (uint32_t)(t & 1) * 8, (uint32_t)((t >> 1) & 1));

        uint32_t curB = sb + SM_B0 + ((t & 1) ? 20480u : 0u);
        if (u < 8) {
            gemm_chunk<4>(sb + ((t & 1) ? SM_A1B : SM_A1A), curB, mh, ns, lane, acc);
        } else if (u == 8) {
            gemm_chunk<4>(sb + SM_A2, curB, mh, ns, lane, acc);
        } else if (u == 9) {
            gemm_chunk<4>(sb + SM_A2 + 16384, curB, mh, ns, lane, acc);
        } else {
            gemm_chunk<2>(sb + (uint32_t)a2c2, curB, mh, ns, lane, acc);  // k 128..159
        }

        if (u == 7) {
            // epilogue 1 (acc is per-warp complete): A2 = bf16(relu(acc+HI+HJ)),
            // then reset acc. Next loop-top sync publishes A2 before gemm(8).
            const float* hjb = g_HJ + (b * N_ + jb) * HS;
#pragma unroll
            for (int mt = 0; mt < 4; mt++) {
                int r0 = mh * 64 + mt * 16 + (lane >> 2);
#pragma unroll
                for (int nt = 0; nt < 5; nt++) {
                    int h = ns * 40 + nt * 8 + (lane & 3) * 2;
                    float2 hi2 = *(const float2*)(smf + SM_HI / 4 + h);
                    float2 hj0 = *(const float2*)(hjb + r0 * HS + h);
                    float2 hj8 = *(const float2*)(hjb + (r0 + 8) * HS + h);
                    float v0 = fmaxf(acc[mt][nt][0] + hi2.x + hj0.x, 0.f);
                    float v1 = fmaxf(acc[mt][nt][1] + hi2.y + hj0.y, 0.f);
                    float v2 = fmaxf(acc[mt][nt][2] + hi2.x + hj8.x, 0.f);
                    float v3 = fmaxf(acc[mt][nt][3] + hi2.y + hj8.y, 0.f);
                    int base = (h < 64) ? SM_A2 : (h < 128) ? (SM_A2 + 16384) : a2c2;
                    int kk = h & 63;
                    uint32_t pk;
                    CVT_BF2(pk, v0, v1);
                    *(uint32_t*)(smc + base + swz(r0, kk)) = pk;
                    CVT_BF2(pk, v2, v3);
                    *(uint32_t*)(smc + base + swz(r0 + 8, kk)) = pk;
                    acc[mt][nt][0] = acc[mt][nt][1] = acc[mt][nt][2] = acc[mt][nt][3] = 0.f;
                }
            }
        } else if (u == 10) {
            // epilogue 2: relu(acc + b2) . w3, cross-warp reduce, write out
            float rs0[4], rs8[4];
#pragma unroll
            for (int mt = 0; mt < 4; mt++) {
                float s0 = 0.f, s8 = 0.f;
#pragma unroll
                for (int nt = 0; nt < 5; nt++) {
                    int h = ns * 40 + nt * 8 + (lane & 3) * 2;
                    float w30 = smf[SM_W3 / 4 + h], w31 = smf[SM_W3 / 4 + h + 1];
                    float bb0 = smf[SM_B2 / 4 + h], bb1 = smf[SM_B2 / 4 + h + 1];
                    s0 += fmaxf(acc[mt][nt][0] + bb0, 0.f) * w30
                        + fmaxf(acc[mt][nt][1] + bb1, 0.f) * w31;
                    s8 += fmaxf(acc[mt][nt][2] + bb0, 0.f) * w30
                        + fmaxf(acc[mt][nt][3] + bb1, 0.f) * w31;
                }
                s0 += __shfl_xor_sync(0xffffffffu, s0, 1);
                s0 += __shfl_xor_sync(0xffffffffu, s0, 2);
                s8 += __shfl_xor_sync(0xffffffffu, s8, 1);
                s8 += __shfl_xor_sync(0xffffffffu, s8, 2);
                rs0[mt] = s0; rs8[mt] = s8;
            }
            if ((lane & 3) == 0) {
                int rr = lane >> 2;
#pragma unroll
                for (int mt = 0; mt < 4; mt++) {
                    smf[SM_RED / 4 + (mh * 64 + mt * 16 + rr) * 4 + ns] = rs0[mt];
                    smf[SM_RED / 4 + (mh * 64 + mt * 16 + 8 + rr) * 4 + ns] = rs8[mt];
                }
            }
            __syncthreads();
            if (tid < 128) {
                float s = smf[SM_RED / 4 + tid * 4 + 0] + smf[SM_RED / 4 + tid * 4 + 1]
                        + smf[SM_RED / 4 + tid * 4 + 2] + smf[SM_RED / 4 + tid * 4 + 3];
                int j = jb + tid;
                out[rowi * N_ + j] = (mi + ment[b * N_ + j] + s + b3v) * (1.0f / 3.0f);
            }
        }
    }
}

// ---------------------------------------------------------------------------
extern "C" void kernel_launch(void* const* d_in, const int* in_sizes, int n_in,
                              void* d_out, int out_size)
{
    const float* g  = (const float*)d_in[0];
    const float* m  = (const float*)d_in[1];
    const float* W1 = (const float*)d_in[2];
    const float* b1 = (const float*)d_in[3];
    const float* W2 = (const float*)d_in[4];
    const float* b2 = (const float*)d_in[5];
    const float* W3 = (const float*)d_in[6];
    const float* b3 = (const float*)d_in[7];
    float* out = (float*)d_out;

    (void)cudaFuncSetAttribute(k_main,
                               cudaFuncAttributeMaxDynamicSharedMemorySize, SMEM_BYTES);

    k_zero<<<(B_ * N_ * HS + 255) / 256, 256>>>();
    k_prep<<<695, 256>>>(g, W1, b1, W2);
    k_main<<<B_ * N_, 256, SMEM_BYTES>>>(g, m, b2, W3, b3, out);
}

// round 15
// speedup vs baseline: 1.5533x; 1.0914x over previous
#include <cuda_runtime.h>
#include <cuda_bf16.h>
#include <cstdint>

// PairwiseScore via warp-level bf16 mma.sync, bulk-copy pipelined.
// out[b,i,j] = (m_i + m_j + MLP3(g_i,g_j))/3,  B=2,N=256,E=512,H=150 (pad 160).
// One CTA per (b,i), 256 threads (8 warps), j-tiles of 128.
// GEMM1 A tiles are RAW bf16(g) (bulk-copied, CTA-independent); the per-i
// gi scaling is applied to the A fragments in registers (MULB2) inside the
// MMA loop: (G .* 1 gi^T) @ W  ==  fragment-scaled MMA. No a_fill pass.
// Per chunk ONE mbarrier phase covers B bulk (20KB) + A bulk (16KB, GEMM1).
// Epilogue-1 at end of u==7; GEMM2 third k-chunk half-width, A tile aliases
// the idle A1 buffer (jt-dep). HI/HJ prep is E-split 8-way with atomicAdd.

namespace {
constexpr int B_ = 2, N_ = 256, E_ = 512, H_ = 150;
constexpr int HS = 160;   // padded H
}

// ---- device scratch (no cudaMalloc allowed) ----
__device__ float g_HI[B_ * N_ * HS];
__device__ float g_HJ[B_ * N_ * HS];
// W1c^T bf16 pre-swizzled: 8 chunks x [160 n][64 k] (20480 B each)
__device__ __align__(16) unsigned char g_W1cT[8 * 20480];
// W2^T bf16 pre-swizzled: 3 chunks x [160 n][64 k]
__device__ __align__(16) unsigned char g_W2T[3 * 20480];
// g bf16 pre-swizzled A-tiles: 32 tiles [(b*2+jt)*8+u] x [128 r][8 seg'] x 16B
__device__ __align__(16) unsigned char g_sw[32 * 16384];

// swizzled byte offset inside a [rows][64] bf16 tile (128 B rows, 8x16B segs)
__device__ __forceinline__ int swz(int row, int k) {
    return row * 128 + (((k >> 3) ^ (row & 7)) * 16) + (k & 7) * 2;
}
__device__ __forceinline__ uint32_t smem_u32(const void* p) {
    uint32_t a;
    asm("{ .reg .u64 t; cvta.to.shared.u64 t, %1; cvt.u32.u64 %0, t; }" : "=r"(a) : "l"(p));
    return a;
}
#define CVT_BF2(res, lo, hi) asm("cvt.rn.bf16x2.f32 %0, %1, %2;" : "=r"(res) : "f"(hi), "f"(lo))
#define MULB2(res, a, b) asm("mul.bf16x2 %0, %1, %2;" : "=r"(res) : "r"(a), "r"(b))

#define MBAR_INIT(mb, c) \
    asm volatile("mbarrier.init.shared.b64 [%0], %1;" :: "r"(mb), "r"(c) : "memory")
#define MBAR_EXPECT_TX(mb, bytes) \
    asm volatile("mbarrier.arrive.expect_tx.shared.b64 _, [%0], %1;" :: "r"(mb), "r"(bytes) : "memory")
#define BULK_G2S(dst, src, bytes, mb) \
    asm volatile("cp.async.bulk.shared::cluster.global.mbarrier::complete_tx::bytes [%0], [%1], %2, [%3];" \
                 :: "r"(dst), "l"(src), "r"(bytes), "r"(mb) : "memory")

__device__ __forceinline__ void mbar_wait(uint32_t mb, uint32_t parity) {
    uint32_t done;
    asm volatile(
        "{\n\t.reg .pred p;\n\t"
        "mbarrier.try_wait.parity.acquire.cta.shared::cta.b64 p, [%1], %2;\n\t"
        "selp.b32 %0, 1, 0, p;\n\t}"
        : "=r"(done) : "r"(mb), "r"(parity) : "memory");
    if (!done) {
        asm volatile(
            "{\n\t.reg .pred P1;\n\t"
            "WL_%=:\n\t"
            "mbarrier.try_wait.parity.acquire.cta.shared::cta.b64 P1, [%0], %1, 0x989680;\n\t"
            "@P1 bra.uni WD_%=;\n\t"
            "bra.uni WL_%=;\n\t"
            "WD_%=:\n\t}"
            :: "r"(mb), "r"(parity) : "memory");
    }
}

__device__ __forceinline__ void mma16816(float* d, const uint32_t* a, const uint32_t* bf) {
    asm volatile("mma.sync.aligned.m16n8k16.row.col.f32.bf16.bf16.f32 "
                 "{%0,%1,%2,%3}, {%4,%5,%6,%7}, {%8,%9}, {%0,%1,%2,%3};"
                 : "+f"(d[0]), "+f"(d[1]), "+f"(d[2]), "+f"(d[3])
                 : "r"(a[0]), "r"(a[1]), "r"(a[2]), "r"(a[3]), "r"(bf[0]), "r"(bf[1]));
}

// B-fragment loads for one ks step: warp (ns) slice, 5 n-tiles.
__device__ __forceinline__ void load_b_frags(uint32_t bBase, int ns, int lane, int ks,
                                             uint32_t (*bfr)[2]) {
#pragma unroll
    for (int ntp = 0; ntp < 2; ntp++) {     // nt pairs (0,1),(2,3) via x4
        int grp = lane >> 3;
        int ntv = ntp * 2 + (grp >> 1);
        int seg = ks * 2 + (grp & 1);
        int nrow = ns * 40 + ntv * 8 + (lane & 7);
        uint32_t bd = bBase + nrow * 128 + ((seg ^ (nrow & 7)) * 16);
        asm volatile("ldmatrix.sync.aligned.m8n8.x4.shared.b16 {%0,%1,%2,%3}, [%4];"
                     : "=r"(bfr[ntp * 2][0]), "=r"(bfr[ntp * 2][1]),
                       "=r"(bfr[ntp * 2 + 1][0]), "=r"(bfr[ntp * 2 + 1][1])
                     : "r"(bd));
    }
    {                                        // nt = 4 via x2
        int nrow = ns * 40 + 32 + (lane & 7);
        int seg = ks * 2 + ((lane >> 3) & 1);
        uint32_t bd = bBase + nrow * 128 + ((seg ^ (nrow & 7)) * 16);
        asm volatile("ldmatrix.sync.aligned.m8n8.x2.shared.b16 {%0,%1}, [%2];"
                     : "=r"(bfr[4][0]), "=r"(bfr[4][1]) : "r"(bd));
    }
}

// Plain chunk (GEMM2): A from smem swizzled tile, NKS ks-steps of 16.
template <int NKS>
__device__ __forceinline__ void gemm_chunk(uint32_t aBase, uint32_t bBase,
                                           int mh, int ns, int lane, float (*acc)[5][4]) {
#pragma unroll
    for (int ks = 0; ks < NKS; ks++) {
        uint32_t a[4][4];
#pragma unroll
        for (int mt = 0; mt < 4; mt++) {
            int row = mh * 64 + mt * 16 + ((lane >> 3) & 1) * 8 + (lane & 7);
            int seg = ks * 2 + (lane >> 4);
            uint32_t ad = aBase + row * 128 + ((seg ^ (row & 7)) * 16);
            asm volatile("ldmatrix.sync.aligned.m8n8.x4.shared.b16 {%0,%1,%2,%3}, [%4];"
                         : "=r"(a[mt][0]), "=r"(a[mt][1]), "=r"(a[mt][2]), "=r"(a[mt][3])
                         : "r"(ad));
        }
        uint32_t bfr[5][2];
        load_b_frags(bBase, ns, lane, ks, bfr);
#pragma unroll
        for (int nt = 0; nt < 5; nt++)
#pragma unroll
            for (int mt = 0; mt < 4; mt++) mma16816(acc[mt][nt], a[mt], bfr[nt]);
    }
}

// GEMM1 chunk: A = raw bf16(g_j) tile; gi scaling applied to fragments.
// gib points at bf16 gi values for this chunk (64 k, 128 B).
// Fragment k-map: regs{0,1} -> k = ks*16+(lane&3)*2 ; regs{2,3} -> +8.
__device__ __forceinline__ void gemm_chunk_s(uint32_t aBase, uint32_t bBase,
                                             const char* gib,
                                             int mh, int ns, int lane, float (*acc)[5][4]) {
#pragma unroll
    for (int ks = 0; ks < 4; ks++) {
        uint32_t gia = *(const uint32_t*)(gib + ks * 32 + (lane & 3) * 4);
        uint32_t gbb = *(const uint32_t*)(gib + ks * 32 + 16 + (lane & 3) * 4);
        uint32_t a[4][4];
#pragma unroll
        for (int mt = 0; mt < 4; mt++) {
            int row = mh * 64 + mt * 16 + ((lane >> 3) & 1) * 8 + (lane & 7);
            int seg = ks * 2 + (lane >> 4);
            uint32_t ad = aBase + row * 128 + ((seg ^ (row & 7)) * 16);
            asm volatile("ldmatrix.sync.aligned.m8n8.x4.shared.b16 {%0,%1,%2,%3}, [%4];"
                         : "=r"(a[mt][0]), "=r"(a[mt][1]), "=r"(a[mt][2]), "=r"(a[mt][3])
                         : "r"(ad));
            MULB2(a[mt][0], a[mt][0], gia);
            MULB2(a[mt][1], a[mt][1], gia);
            MULB2(a[mt][2], a[mt][2], gbb);
            MULB2(a[mt][3], a[mt][3], gbb);
        }
        uint32_t bfr[5][2];
        load_b_frags(bBase, ns, lane, ks, bfr);
#pragma unroll
        for (int nt = 0; nt < 5; nt++)
#pragma unroll
            for (int mt = 0; mt < 4; mt++) mma16816(acc[mt][nt], a[mt], bfr[nt]);
    }
}

// smem byte map
constexpr int SM_HI  = 0;        // 160 f (640 B)
constexpr int SM_W3  = 640;      // 160 f
constexpr int SM_B2  = 1280;     // 160 f
constexpr int SM_GIB = 1920;     // 512 bf16 (1024 B)
constexpr int SM_RED = 2944;     // 128*4 f (2048 B)
constexpr int SM_MBAR = 4992;    // 2 mbarriers (16 B)
constexpr int SM_A1A = 5120;     // A1 buf 0 (16384); aliases A2 chunk 2 for jt=0
constexpr int SM_A1B = 21504;    // A1 buf 1 (16384); aliases A2 chunk 2 for jt=1
constexpr int SM_B0  = 37888;    // [160][64] bf16 swz (20480) x2 double buffer
constexpr int SM_A2  = 78848;    // A2 chunks 0,1 (2 x 16384)
constexpr int SMEM_BYTES = 111616;

// ---------------------------------------------------------------------------
// k_zero: re-zero g_HI/g_HJ every launch (graph replays; atomics accumulate).
// ---------------------------------------------------------------------------
__global__ void __launch_bounds__(256) k_zero() {
    int i = blockIdx.x * 256 + threadIdx.x;
    if (i < B_ * N_ * HS) {
        g_HI[i] = 0.f;
        g_HJ[i] = 0.f;
    }
}

// ---------------------------------------------------------------------------
// Merged prep kernel.
// bb 0..1023   : HI/HJ, E-split 8-way: gb=bb>>3 (4 rows), ec8=bb&7 (64-wide E);
//                partials via atomicAdd (b1 added by ec8==0 only).
// bb 1024..1063: W1cT (vectorized uint4 stores)
// bb 1064..1078: W2T
// bb 1079..1206: g -> g_sw bf16 pre-swizzled A tiles
// ---------------------------------------------------------------------------
__global__ void __launch_bounds__(256) k_prep(
    const float* __restrict__ g, const float* __restrict__ W1,
    const float* __restrict__ b1, const float* __restrict__ W2)
{
    const int bb = blockIdx.x;
    const int tid = threadIdx.x;
    if (bb >= 1024) {
        if (bb < 1064) {          // W1cT: pack 8 bf16 = one 16B swizzle seg
            int idx = (bb - 1024) * 256 + tid;          // 0..10239
            int c = idx / 1280, r = idx % 1280;
            int s = r / 160, n = r % 160;
            const float* src = W1 + (2 * E_ + c * 64 + s * 8) * H_ + n;
            uint4 o;
            uint32_t* op = (uint32_t*)&o;
            bool v = (n < H_);
#pragma unroll
            for (int d = 0; d < 4; d++) {
                float lo = v ? src[(2 * d) * H_] : 0.f;
                float hi = v ? src[(2 * d + 1) * H_] : 0.f;
                CVT_BF2(op[d], lo, hi);
            }
            *(uint4*)(g_W1cT + c * 20480 + n * 128 + ((s ^ (n & 7)) * 16)) = o;
        } else if (bb < 1079) {   // W2T
            int idx = (bb - 1064) * 256 + tid;          // 0..3839
            int c = idx / 1280, r = idx % 1280;
            int s = r / 160, n = r % 160;
            int k0 = c * 64 + s * 8;
            const float* src = W2 + k0 * H_ + n;
            uint4 o;
            uint32_t* op = (uint32_t*)&o;
            bool v = (n < H_);
#pragma unroll
            for (int d = 0; d < 4; d++) {
                float lo = (v && k0 + 2 * d < H_) ? src[(2 * d) * H_] : 0.f;
                float hi = (v && k0 + 2 * d + 1 < H_) ? src[(2 * d + 1) * H_] : 0.f;
                CVT_BF2(op[d], lo, hi);
            }
            *(uint4*)(g_W2T + c * 20480 + n * 128 + ((s ^ (n & 7)) * 16)) = o;
        } else {                  // g_sw
            int slot = (bb - 1079) * 256 + tid;         // 32768 16B slots
            int tile = slot >> 10, q = slot & 1023;
            int r = q >> 3, sp = q & 7;
            int b = tile >> 4, jt = (tile >> 3) & 1, u = tile & 7;
            int grow = b * 256 + jt * 128 + r;
            int e0 = u * 64 + ((sp ^ (r & 7)) * 8);
            const float4* src = (const float4*)(g + grow * E_ + e0);
            float4 v0 = src[0], v1 = src[1];
            uint4 o;
            CVT_BF2(o.x, v0.x, v0.y);
            CVT_BF2(o.y, v0.z, v0.w);
            CVT_BF2(o.z, v1.x, v1.y);
            CVT_BF2(o.w, v1.z, v1.w);
            *(uint4*)(g_sw + slot * 16) = o;
        }
        return;
    }
    // HI/HJ partial: 4 rows, E window [ec8*64, ec8*64+64)
    __shared__ float sm[4 * 33 + 2 * 32 * 152 + 32];
    float* gs = sm;
    float* wa = sm + 4 * 33;
    float* wb = wa + 32 * 152;
    const int tx = tid & 63, ty = tid >> 6;
    const int gb = bb >> 3, ec8 = bb & 7;
    const int r0 = gb * 4;
    const int e_base = ec8 * 64;
    const bool v2 = (tx < 22);    // h = tx+128 < 150
    float aA[3] = {0, 0, 0}, aB[3] = {0, 0, 0};
    for (int ec = e_base; ec < e_base + 64; ec += 32) {
        __syncthreads();
        if (tid < 128) {
            int jj = tid >> 5, ee = tid & 31;
            gs[jj * 33 + ee] = g[(r0 + jj) * E_ + ec + ee];
        }
        for (int q = tid; q < 32 * H_; q += 256) {
            int r = q / H_, c = q % H_;
            wa[r * 152 + c] = W1[(ec + r) * H_ + c];
            wb[r * 152 + c] = W1[(E_ + ec + r) * H_ + c];
        }
        __syncthreads();
#pragma unroll 8
        for (int e = 0; e < 32; e++) {
            float a = gs[ty * 33 + e];
            aA[0] += a * wa[e * 152 + tx];
            aA[1] += a * wa[e * 152 + tx + 64];
            if (v2) aA[2] += a * wa[e * 152 + tx + 128];
            aB[0] += a * wb[e * 152 + tx];
            aB[1] += a * wb[e * 152 + tx + 64];
            if (v2) aB[2] += a * wb[e * 152 + tx + 128];
        }
    }
    const int row = r0 + ty;
    const float bb0 = (ec8 == 0) ? b1[tx] : 0.f;
    const float bb1 = (ec8 == 0) ? b1[tx + 64] : 0.f;
    atomicAdd(&g_HI[row * HS + tx], aA[0] + bb0);
    atomicAdd(&g_HJ[row * HS + tx], aB[0]);
    atomicAdd(&g_HI[row * HS + tx + 64], aA[1] + bb1);
    atomicAdd(&g_HJ[row * HS + tx + 64], aB[1]);
    if (v2) {
        int h2 = tx + 128;
        const float bb2 = (ec8 == 0) ? b1[h2] : 0.f;
        atomicAdd(&g_HI[row * HS + h2], aA[2] + bb2);
        atomicAdd(&g_HJ[row * HS + h2], aB[2]);
    }
}

// ---------------------------------------------------------------------------
// Main kernel: one CTA per (b,i), 256 threads (8 warps), 2 CTAs/SM.
// ---------------------------------------------------------------------------
__global__ void __launch_bounds__(256, 2) k_main(
    const float* __restrict__ g, const float* __restrict__ ment,
    const float* __restrict__ b2, const float* __restrict__ W3,
    const float* __restrict__ b3, float* __restrict__ out)
{
    extern __shared__ char smc[];
    float* smf = (float*)smc;
    const uint32_t sb = smem_u32(smc);
    const int tid = threadIdx.x, w = tid >> 5, lane = tid & 31;
    const int mh = w & 1, ns = w >> 1;
    const int b = blockIdx.x >> 8;
    const int rowi = blockIdx.x;

    if (tid == 0) {
        MBAR_INIT(sb + SM_MBAR, 1);
        MBAR_INIT(sb + SM_MBAR + 8, 1);
    }
    __syncthreads();          // mbarrier init visible
    if (tid == 0) {           // chunk 0: B (W1c c0) + A (raw g tile) bulks
        MBAR_EXPECT_TX(sb + SM_MBAR, 36864u);
        BULK_G2S(sb + SM_B0, (const char*)g_W1cT, 20480u, sb + SM_MBAR);
        BULK_G2S(sb + SM_A1A, (const char*)g_sw + (b * 2) * 8 * 16384, 16384u,
                 sb + SM_MBAR);
    }

    {   // gi -> bf16 in smem (read by gemm_chunk_s fragment scaling)
        float2 v = *(const float2*)(g + rowi * E_ + tid * 2);
        uint32_t pk;
        CVT_BF2(pk, v.x, v.y);
        *(uint32_t*)(smc + SM_GIB + tid * 4) = pk;
    }
    for (int q = tid; q < HS; q += 256) {
        smf[SM_HI / 4 + q] = g_HI[rowi * HS + q];   // already zero-padded
        smf[SM_W3 / 4 + q] = (q < H_) ? W3[q] : 0.f;
        smf[SM_B2 / 4 + q] = (q < H_) ? b2[q] : 0.f;
    }

    const float mi = ment[rowi];
    const float b3v = b3[0];
    float acc[4][5][4];   // shared between GEMM1 and GEMM2 (reset at u==0 / epi-1)

    for (int t = 0; t < 22; t++) {
        const int u = (t >= 11) ? t - 11 : t;        // chunk id in j-tile stream
        const int jt = (t >= 11) ? 1 : 0;
        const int jb = jt * 128;
        // A2 chunk-2 alias: the A1 buffer idle during this j-tile's GEMM2 span
        const int a2c2 = jt ? SM_A1B : SM_A1A;

        __syncthreads();   // gemm(t-1)+epi(t-1) done; gi/HI (t=0) visible

        // issue bulk copies for chunk t+1 into alternate buffer set
        if (t + 1 < 22) {
            const int t2 = t + 1;
            const int u2 = (t2 >= 11) ? t2 - 11 : t2;
            const int jt2 = (t2 >= 11) ? 1 : 0;
            if (tid == 0) {
                uint32_t mb2 = sb + SM_MBAR + (uint32_t)(t2 & 1) * 8;
                MBAR_EXPECT_TX(mb2, 20480u + ((u2 < 8) ? 16384u : 0u));
                const char* srcB = (u2 < 8) ? (const char*)g_W1cT + u2 * 20480
                                            : (const char*)g_W2T + (u2 - 8) * 20480;
                BULK_G2S(sb + SM_B0 + ((t2 & 1) ? 20480u : 0u), srcB, 20480u, mb2);
                if (u2 < 8)
                    BULK_G2S(sb + ((t2 & 1) ? SM_A1B : SM_A1A),
                             (const char*)g_sw + ((b * 2 + jt2) * 8 + u2) * 16384,
                             16384u, mb2);
            }
        }

        if (u == 0) {
#pragma unroll
            for (int mt = 0; mt < 4; mt++)
#pragma unroll
                for (int nt = 0; nt < 5; nt++)
#pragma unroll
                    for (int q = 0; q < 4; q++) acc[mt][nt][q] = 0.f;
        }

        // wait for chunk t's bulk copies (parity: load number (t>>1) on this mbar)
        mbar_wait(sb + SM_MBAR + (uint32_t)(t & 1) * 8, (uint32_t)((t >> 1) & 1));

        uint32_t curB = sb + SM_B0 + ((t & 1) ? 20480u : 0u);
        if (u < 8) {
            gemm_chunk_s(sb + ((t & 1) ? SM_A1B : SM_A1A), curB,
                         smc + SM_GIB + u * 128, mh, ns, lane, acc);
        } else if (u == 8) {
            gemm_chunk<4>(sb + SM_A2, curB, mh, ns, lane, acc);
        } else if (u == 9) {
            gemm_chunk<4>(sb + SM_A2 + 16384, curB, mh, ns, lane, acc);
        } else {
            gemm_chunk<2>(sb + (uint32_t)a2c2, curB, mh, ns, lane, acc);  // k 128..159
        }

        if (u == 7) {
            // epilogue 1 (acc per-warp complete): A2 = bf16(relu(acc+HI+HJ)),
            // then reset acc. Next loop-top sync publishes A2 before gemm(8).
            const float* hjb = g_HJ + (b * N_ + jb) * HS;
#pragma unroll
            for (int mt = 0; mt < 4; mt++) {
                int r0 = mh * 64 + mt * 16 + (lane >> 2);
#pragma unroll
                for (int nt = 0; nt < 5; nt++) {
                    int h = ns * 40 + nt * 8 + (lane & 3) * 2;
                    float2 hi2 = *(const float2*)(smf + SM_HI / 4 + h);
                    float2 hj0 = *(const float2*)(hjb + r0 * HS + h);
                    float2 hj8 = *(const float2*)(hjb + (r0 + 8) * HS + h);
                    float v0 = fmaxf(acc[mt][nt][0] + hi2.x + hj0.x, 0.f);
                    float v1 = fmaxf(acc[mt][nt][1] + hi2.y + hj0.y, 0.f);
                    float v2 = fmaxf(acc[mt][nt][2] + hi2.x + hj8.x, 0.f);
                    float v3 = fmaxf(acc[mt][nt][3] + hi2.y + hj8.y, 0.f);
                    int base = (h < 64) ? SM_A2 : (h < 128) ? (SM_A2 + 16384) : a2c2;
                    int kk = h & 63;
                    uint32_t pk;
                    CVT_BF2(pk, v0, v1);
                    *(uint32_t*)(smc + base + swz(r0, kk)) = pk;
                    CVT_BF2(pk, v2, v3);
                    *(uint32_t*)(smc + base + swz(r0 + 8, kk)) = pk;
                    acc[mt][nt][0] = acc[mt][nt][1] = acc[mt][nt][2] = acc[mt][nt][3] = 0.f;
                }
            }
        } else if (u == 10) {
            // epilogue 2: relu(acc + b2) . w3, cross-warp reduce, write out
            float rs0[4], rs8[4];
#pragma unroll
            for (int mt = 0; mt < 4; mt++) {
                float s0 = 0.f, s8 = 0.f;
#pragma unroll
                for (int nt = 0; nt < 5; nt++) {
                    int h = ns * 40 + nt * 8 + (lane & 3) * 2;
                    float w30 = smf[SM_W3 / 4 + h], w31 = smf[SM_W3 / 4 + h + 1];
                    float bb0 = smf[SM_B2 / 4 + h], bb1 = smf[SM_B2 / 4 + h + 1];
                    s0 += fmaxf(acc[mt][nt][0] + bb0, 0.f) * w30
                        + fmaxf(acc[mt][nt][1] + bb1, 0.f) * w31;
                    s8 += fmaxf(acc[mt][nt][2] + bb0, 0.f) * w30
                        + fmaxf(acc[mt][nt][3] + bb1, 0.f) * w31;
                }
                s0 += __shfl_xor_sync(0xffffffffu, s0, 1);
                s0 += __shfl_xor_sync(0xffffffffu, s0, 2);
                s8 += __shfl_xor_sync(0xffffffffu, s8, 1);
                s8 += __shfl_xor_sync(0xffffffffu, s8, 2);
                rs0[mt] = s0; rs8[mt] = s8;
            }
            if ((lane & 3) == 0) {
                int rr = lane >> 2;
#pragma unroll
                for (int mt = 0; mt < 4; mt++) {
                    smf[SM_RED / 4 + (mh * 64 + mt * 16 + rr) * 4 + ns] = rs0[mt];
                    smf[SM_RED / 4 + (mh * 64 + mt * 16 + 8 + rr) * 4 + ns] = rs8[mt];
                }
            }
            __syncthreads();
            if (tid < 128) {
                float s = smf[SM_RED / 4 + tid * 4 + 0] + smf[SM_RED / 4 + tid * 4 + 1]
                        + smf[SM_RED / 4 + tid * 4 + 2] + smf[SM_RED / 4 + tid * 4 + 3];
                int j = jb + tid;
                out[rowi * N_ + j] = (mi + ment[b * N_ + j] + s + b3v) * (1.0f / 3.0f);
            }
        }
    }
}

// ---------------------------------------------------------------------------
extern "C" void kernel_launch(void* const* d_in, const int* in_sizes, int n_in,
                              void* d_out, int out_size)
{
    const float* g  = (const float*)d_in[0];
    const float* m  = (const float*)d_in[1];
    const float* W1 = (const float*)d_in[2];
    const float* b1 = (const float*)d_in[3];
    const float* W2 = (const float*)d_in[4];
    const float* b2 = (const float*)d_in[5];
    const float* W3 = (const float*)d_in[6];
    const float* b3 = (const float*)d_in[7];
    float* out = (float*)d_out;

    (void)cudaFuncSetAttribute(k_main,
                               cudaFuncAttributeMaxDynamicSharedMemorySize, SMEM_BYTES);

    k_zero<<<(B_ * N_ * HS + 255) / 256, 256>>>();
    k_prep<<<1207, 256>>>(g, W1, b1, W2);
    k_main<<<B_ * N_, 256, SMEM_BYTES>>>(g, m, b2, W3, b3, out);
}